// round 12
// baseline (speedup 1.0000x reference)
#include <cuda_runtime.h>
#include <cuda_bf16.h>
#include <cstdint>

#define TT 8192
#define DD 64
#define MM 4
#define SEG 4096

// ---------------- scratch (device globals; no allocation) ----------------
__device__ float g_Q [TT * DD];            // Q row-major [t][d]           2MB
__device__ float g_KT[MM * DD * TT];       // K transposed [m][d][t]       8MB
__device__ float g_V2[MM * TT * 2];        // V interleaved [m][t][e]      256KB
__device__ float g_T2[MM * TT];            // t2 per modality (t1 = m=0)
__device__ int   g_idx[MM * TT];           // searchsorted results
__device__ float g_S [MM * DD * TT * 2];   // prefix sums [m][d][t][e]     16MB
__device__ uint4 g_WF[15 * 1024];          // W fragments [u*3+l][(ks*8+nt)*32+lane]

// ---------------- bf16 split helpers ----------------
__device__ __forceinline__ uint32_t pk(unsigned short a, unsigned short b) {
    return (uint32_t)a | ((uint32_t)b << 16);
}
__device__ __forceinline__ void split2(float fx, float fy, uint32_t& h, uint32_t& l) {
    __nv_bfloat16 h0 = __float2bfloat16(fx), h1 = __float2bfloat16(fy);
    h = pk(__bfloat16_as_ushort(h0), __bfloat16_as_ushort(h1));
    l = pk(__bfloat16_as_ushort(__float2bfloat16(fx - __bfloat162float(h0))),
           __bfloat16_as_ushort(__float2bfloat16(fy - __bfloat162float(h1))));
}
__device__ __forceinline__ void mma_bf16(float* d, uint32_t a0, uint32_t a1,
                                         uint32_t a2, uint32_t a3,
                                         uint32_t b0, uint32_t b1) {
    asm volatile(
        "mma.sync.aligned.m16n8k16.row.col.f32.bf16.bf16.f32 "
        "{%0,%1,%2,%3},{%4,%5,%6,%7},{%8,%9},{%0,%1,%2,%3};"
        : "+f"(d[0]), "+f"(d[1]), "+f"(d[2]), "+f"(d[3])
        : "r"(a0), "r"(a1), "r"(a2), "r"(a3), "r"(b0), "r"(b1));
}

// AFRAG: [h/l][ks][w][lane] uint4   -> 2048 uint4 = 32KB
// WFRAG: double-buffered [ks][nt][lane] -> 2 x 1024 uint4 = 32KB
#define MLP_SMEM (4096 * 16)

// ---------------- Kernel 0: precompute W fragments (one block per (u,l)) --
__global__ void __launch_bounds__(256) k_wprep(
    const float* __restrict__ wq_w, const float* __restrict__ wk_w)
{
    const int ul = blockIdx.x;          // 0..14
    const int u = ul / 3, l = ul % 3;
    const float* W = (u == 0) ? wq_w : wk_w + (size_t)(u - 1) * 3 * DD * DD;
    const float* Wlay = W + (size_t)l * DD * DD;

    const int tid = threadIdx.x;
    const int w = tid >> 5, lane = tid & 31;
    const int g = lane >> 2, q = lane & 3;
    const int n = w * 8 + g;

    #pragma unroll
    for (int ks = 0; ks < 4; ks++) {
        const float* wp = Wlay + (ks * 16 + 2 * q) * 64 + n;
        float b00 = wp[0],      b01 = wp[64];
        float b10 = wp[8 * 64], b11 = wp[9 * 64];
        uint4 v;
        split2(b00, b01, v.x, v.z);
        split2(b10, b11, v.y, v.w);
        g_WF[ul * 1024 + (ks * 8 + w) * 32 + lane] = v;
    }
}

// ---------------- Kernel 1: 5 MLPs, fragment-resident smem -----------------
// grid (T/128, 5), 256 threads (8 warps); warp w owns rows w*16 .. w*16+15.
__global__ void __launch_bounds__(256, 3) k_mlp(
    const float* __restrict__ X,
    const float* __restrict__ wq_b, const float* __restrict__ wk_b)
{
    extern __shared__ __align__(16) uint4 sm4[];
    uint4* A4 = sm4;            // [h][ks][w][lane]
    uint4* W4 = sm4 + 2048;     // 2 buffers of [ks][nt][lane]
    float* St = (float*)sm4;    // final-layer staging (reuses everything)
    __shared__ float s_bias[3 * 64];

    const int tid  = threadIdx.x;
    const int w    = tid >> 5;
    const int lane = tid & 31;
    const int g    = lane >> 2;   // 0..7
    const int q    = lane & 3;    // 0..3
    const int u    = blockIdx.y;
    const int base = blockIdx.x * 128;
    const int m_in = (u == 0) ? 0 : (u - 1);
    const float* B = (u == 0) ? wq_b : wk_b + (size_t)(u - 1) * 3 * DD;

    for (int i = tid; i < 192; i += 256) s_bias[i] = B[i];

    // ---- initial A fragments straight from X (warp-private region) ----
    {
        const int r0 = base + w * 16 + g;
        const float* x0 = X + ((size_t)m_in * TT + r0) * DD;
        const float* x1 = x0 + 8 * DD;
        #pragma unroll
        for (int ks = 0; ks < 4; ks++) {
            float2 a0 = *(const float2*)(x0 + ks * 16 + 2 * q);
            float2 a2 = *(const float2*)(x0 + ks * 16 + 8 + 2 * q);
            float2 a1 = *(const float2*)(x1 + ks * 16 + 2 * q);
            float2 a3 = *(const float2*)(x1 + ks * 16 + 8 + 2 * q);
            if (u >= 1) {
                if (ks == 0 && q == 0) {
                    ((float2*)g_V2)[(size_t)m_in * TT + r0]     = a0;
                    ((float2*)g_V2)[(size_t)m_in * TT + r0 + 8] = a1;
                }
                if (ks == 3 && q == 3) {            // k = 63 lives in a2.y/a3.y
                    g_T2[(size_t)m_in * TT + r0]     = a2.y;
                    g_T2[(size_t)m_in * TT + r0 + 8] = a3.y;
                }
            }
            uint4 vh, vl;
            split2(a0.x, a0.y, vh.x, vl.x);
            split2(a2.x, a2.y, vh.y, vl.y);
            split2(a1.x, a1.y, vh.z, vl.z);
            split2(a3.x, a3.y, vh.w, vl.w);
            A4[(ks * 8 + w) * 32 + lane]        = vh;
            A4[((4 + ks) * 8 + w) * 32 + lane]  = vl;
        }
    }

    for (int l = 0; l < 3; l++) {
        // ---- coalesced W fragment load from g_WF into buffer (l&1) ----
        uint4* Wb = W4 + (l & 1) * 1024;
        const uint4* wf = g_WF + (u * 3 + l) * 1024;
        #pragma unroll
        for (int j = 0; j < 4; j++)
            Wb[tid + 256 * j] = wf[tid + 256 * j];
        __syncthreads();

        // ---- MMA: 4 ks x 8 nt x 3 (hh, hl, lh) ----
        float d[8][4];
        #pragma unroll
        for (int nt = 0; nt < 8; nt++)
            #pragma unroll
            for (int j = 0; j < 4; j++) d[nt][j] = 0.0f;

        #pragma unroll
        for (int ks = 0; ks < 4; ks++) {
            uint4 ah = A4[(ks * 8 + w) * 32 + lane];
            uint4 al = A4[((4 + ks) * 8 + w) * 32 + lane];
            #pragma unroll
            for (int nt = 0; nt < 8; nt++) {
                uint4 b = Wb[(ks * 8 + nt) * 32 + lane];
                mma_bf16(d[nt], ah.x, ah.z, ah.y, ah.w, b.x, b.y);
                mma_bf16(d[nt], ah.x, ah.z, ah.y, ah.w, b.z, b.w);
                mma_bf16(d[nt], al.x, al.z, al.y, al.w, b.x, b.y);
            }
        }

        if (l < 2) {
            // ---- epilogue -> next layer's A fragments (warp-private, no sync)
            #pragma unroll
            for (int ksn = 0; ksn < 4; ksn++) {
                const int nt0 = 2 * ksn, nt1 = nt0 + 1;
                const int c0 = nt0 * 8 + 2 * q, c1 = nt1 * 8 + 2 * q;
                float f0x = fmaxf(d[nt0][0] + s_bias[l * 64 + c0],     0.0f);
                float f0y = fmaxf(d[nt0][1] + s_bias[l * 64 + c0 + 1], 0.0f);
                float f1x = fmaxf(d[nt1][0] + s_bias[l * 64 + c1],     0.0f);
                float f1y = fmaxf(d[nt1][1] + s_bias[l * 64 + c1 + 1], 0.0f);
                float f2x = fmaxf(d[nt0][2] + s_bias[l * 64 + c0],     0.0f);
                float f2y = fmaxf(d[nt0][3] + s_bias[l * 64 + c0 + 1], 0.0f);
                float f3x = fmaxf(d[nt1][2] + s_bias[l * 64 + c1],     0.0f);
                float f3y = fmaxf(d[nt1][3] + s_bias[l * 64 + c1 + 1], 0.0f);
                uint4 vh, vl;
                split2(f0x, f0y, vh.x, vl.x);
                split2(f1x, f1y, vh.y, vl.y);
                split2(f2x, f2y, vh.z, vl.z);
                split2(f3x, f3y, vh.w, vl.w);
                A4[(ksn * 8 + w) * 32 + lane]       = vh;
                A4[((4 + ksn) * 8 + w) * 32 + lane] = vl;
            }
        } else {
            __syncthreads();   // everyone done with A4/W4 before St overwrite
            const int row0 = w * 16 + g;
            if (u == 0) {
                #pragma unroll
                for (int nt = 0; nt < 8; nt++) {
                    const int col = nt * 8 + 2 * q;
                    St[row0 * 72 + col]           = d[nt][0] + s_bias[128 + col];
                    St[row0 * 72 + col + 1]       = d[nt][1] + s_bias[128 + col + 1];
                    St[(row0 + 8) * 72 + col]     = d[nt][2] + s_bias[128 + col];
                    St[(row0 + 8) * 72 + col + 1] = d[nt][3] + s_bias[128 + col + 1];
                }
                __syncthreads();
                const int row = tid >> 1, c0 = (tid & 1) * 32;
                #pragma unroll
                for (int qq = 0; qq < 8; qq++) {
                    float4 v = *(float4*)&St[row * 72 + c0 + qq * 4];
                    *(float4*)&g_Q[(size_t)(base + row) * 64 + c0 + qq * 4] = v;
                }
            } else {
                #pragma unroll
                for (int nt = 0; nt < 8; nt++) {
                    const int col = nt * 8 + 2 * q;
                    St[col * 132 + row0]           = d[nt][0] + s_bias[128 + col];
                    St[(col + 1) * 132 + row0]     = d[nt][1] + s_bias[128 + col + 1];
                    St[col * 132 + row0 + 8]       = d[nt][2] + s_bias[128 + col];
                    St[(col + 1) * 132 + row0 + 8] = d[nt][3] + s_bias[128 + col + 1];
                }
                __syncthreads();
                const int col = tid >> 2, l4 = tid & 3;
                const size_t cb = (size_t)((u - 1) * 64 + col) * TT + base;
                #pragma unroll
                for (int qq = 0; qq < 8; qq++) {
                    const int row = l4 * 4 + qq * 16;
                    float4 v = *(float4*)&St[col * 132 + row];
                    *(float4*)&g_KT[cb + row] = v;
                }
            }
        }
    }
}

// ---------------- Kernel 2: fused scan (blocks 0..511) + searchsorted (512..639)
__global__ void __launch_bounds__(256) k_scanIdx(float* __restrict__ out)
{
    const int tid = threadIdx.x;

    if (blockIdx.x >= 512) {
        const int gid = (blockIdx.x - 512) * 256 + tid;   // [0, MM*TT)
        if (gid < TT)
            ((float2*)out)[gid] = make_float2(0.0f, 0.0f);
        const int t = gid & (TT - 1);
        const int m = gid >> 13;
        const float key = g_T2[t];
        const float* arr = g_T2 + (size_t)m * TT;
        int lo = 0, hi = TT;
        while (lo < hi) {
            int mid = (lo + hi) >> 1;
            if (arr[mid] <= key) lo = mid + 1; else hi = mid;
        }
        g_idx[gid] = lo - 1;
        return;
    }

    const int ch  = blockIdx.x >> 1;      // m*64+d
    const int seg = blockIdx.x & 1;
    const int m   = ch >> 6;

    const float4* kp = (const float4*)(g_KT + (size_t)ch * TT);
    const float4* vp = (const float4*)(g_V2 + (size_t)m * TT * 2);

    float pre0 = 0.0f, pre1 = 0.0f;
    if (seg) {
        const int pi = tid * 16;
        #pragma unroll
        for (int q = 0; q < 4; q++) {
            float4 k4 = kp[(pi >> 2) + q];
            float4 va = vp[(pi >> 1) + q * 2];
            float4 vb = vp[(pi >> 1) + q * 2 + 1];
            pre0 += k4.x * va.x + k4.y * va.z + k4.z * vb.x + k4.w * vb.z;
            pre1 += k4.x * va.y + k4.y * va.w + k4.z * vb.y + k4.w * vb.w;
        }
    }

    const int t0 = seg * SEG + tid * 16;
    float kk[16];
    #pragma unroll
    for (int q = 0; q < 4; q++) {
        float4 k4 = kp[(t0 >> 2) + q];
        kk[q * 4 + 0] = k4.x; kk[q * 4 + 1] = k4.y;
        kk[q * 4 + 2] = k4.z; kk[q * 4 + 3] = k4.w;
    }
    float p0[16], p1[16];
    #pragma unroll
    for (int q = 0; q < 8; q++) {
        float4 v = vp[(t0 >> 1) + q];
        p0[q * 2]     = kk[q * 2]     * v.x;
        p1[q * 2]     = kk[q * 2]     * v.y;
        p0[q * 2 + 1] = kk[q * 2 + 1] * v.z;
        p1[q * 2 + 1] = kk[q * 2 + 1] * v.w;
    }
    #pragma unroll
    for (int e = 1; e < 16; e++) { p0[e] += p0[e - 1]; p1[e] += p1[e - 1]; }

    const int lane = tid & 31, wid = tid >> 5;
    float s0 = p0[15], s1 = p1[15];
    const float t00 = s0, t11 = s1;
    #pragma unroll
    for (int off = 1; off < 32; off <<= 1) {
        float n0 = __shfl_up_sync(0xffffffffu, s0, off);
        float n1 = __shfl_up_sync(0xffffffffu, s1, off);
        if (lane >= off) { s0 += n0; s1 += n1; }
    }
    float pr0 = pre0, pr1 = pre1;
    if (seg) {
        #pragma unroll
        for (int off = 16; off > 0; off >>= 1) {
            pr0 += __shfl_down_sync(0xffffffffu, pr0, off);
            pr1 += __shfl_down_sync(0xffffffffu, pr1, off);
        }
    }
    __shared__ float ws0[8], ws1[8], wp0[8], wp1[8];
    if (lane == 31) { ws0[wid] = s0; ws1[wid] = s1; }
    if (lane == 0)  { wp0[wid] = pr0; wp1[wid] = pr1; }
    __syncthreads();
    float base0 = 0.0f, base1 = 0.0f;
    #pragma unroll
    for (int w = 0; w < 8; w++) {
        base0 += wp0[w]; base1 += wp1[w];
        if (w < wid) { base0 += ws0[w]; base1 += ws1[w]; }
    }
    base0 += s0 - t00;
    base1 += s1 - t11;

    float4* sp = (float4*)(g_S + (size_t)ch * TT * 2);
    #pragma unroll
    for (int q = 0; q < 8; q++) {
        float4 o;
        o.x = base0 + p0[q * 2];     o.y = base1 + p1[q * 2];
        o.z = base0 + p0[q * 2 + 1]; o.w = base1 + p1[q * 2 + 1];
        sp[(t0 >> 1) + q] = o;
    }
}

// ---------------- Kernel 3: gather + contract + atomic accumulate ---------
__global__ void __launch_bounds__(256) k_gath(float* __restrict__ out)
{
    __shared__ float Qs[64 * 65];
    __shared__ float2 red[256];

    const int m   = blockIdx.y;
    const int t0  = blockIdx.x * 64;
    const int tid = threadIdx.x;
    const int lt  = tid & 63;
    const int dq  = tid >> 6;

    {
        const int r = tid >> 2, c4 = tid & 3;
        const float4* src = (const float4*)(g_Q + (size_t)(t0 + r) * 64 + c4 * 16);
        #pragma unroll
        for (int q = 0; q < 4; q++) {
            float4 v = src[q];
            int d0 = c4 * 16 + q * 4;
            Qs[r * 65 + d0 + 0] = v.x;
            Qs[r * 65 + d0 + 1] = v.y;
            Qs[r * 65 + d0 + 2] = v.z;
            Qs[r * 65 + d0 + 3] = v.w;
        }
    }

    const int idx = g_idx[(size_t)m * TT + t0 + lt];
    __syncthreads();

    float a0 = 0.0f, a1 = 0.0f;
    if (idx >= 0) {
        const float2* sp = (const float2*)g_S + (size_t)(m * 64 + dq * 16) * TT + idx;
        #pragma unroll
        for (int dd = 0; dd < 16; dd++) {
            float q  = Qs[lt * 65 + dq * 16 + dd];
            float2 s = sp[(size_t)dd * TT];
            a0 += q * s.x;
            a1 += q * s.y;
        }
    }
    red[tid] = make_float2(a0, a1);
    __syncthreads();

    if (dq == 0) {
        float ax = 0.0f, ay = 0.0f;
        #pragma unroll
        for (int q = 0; q < 4; q++) {
            float2 v = red[lt + 64 * q];
            ax += v.x; ay += v.y;
        }
        atomicAdd(out + (size_t)(t0 + lt) * 2 + 0, ax);
        atomicAdd(out + (size_t)(t0 + lt) * 2 + 1, ay);
    }
}

// ---------------- launch ----------------
extern "C" void kernel_launch(void* const* d_in, const int* in_sizes, int n_in,
                              void* d_out, int out_size)
{
    const float* X    = (const float*)d_in[0];
    const float* wq_w = (const float*)d_in[1];
    const float* wq_b = (const float*)d_in[2];
    const float* wk_w = (const float*)d_in[3];
    const float* wk_b = (const float*)d_in[4];
    float* out = (float*)d_out;

    cudaFuncSetAttribute(k_mlp, cudaFuncAttributeMaxDynamicSharedMemorySize, MLP_SMEM);

    k_wprep  <<<15, 256>>>(wq_w, wk_w);
    k_mlp    <<<dim3(TT / 128, 5), 256, MLP_SMEM>>>(X, wq_b, wk_b);
    k_scanIdx<<<512 + 128, 256>>>(out);
    k_gath   <<<dim3(TT / 64, MM), 256>>>(out);
}

// round 13
// speedup vs baseline: 1.0875x; 1.0875x over previous
#include <cuda_runtime.h>
#include <cuda_bf16.h>
#include <cstdint>

#define TT 8192
#define DD 64
#define MM 4
#define SEG 4096

// ---------------- scratch (device globals; no allocation) ----------------
__device__ float g_Q [TT * DD];            // Q row-major [t][d]           2MB
__device__ float g_KT[MM * DD * TT];       // K transposed [m][d][t]       8MB
__device__ float g_V2[MM * TT * 2];        // V interleaved [m][t][e]      256KB
__device__ float g_T2[MM * TT];            // t2 per modality (t1 = m=0)
__device__ int   g_idx[MM * TT];           // searchsorted results
__device__ float g_S [MM * DD * TT * 2];   // prefix sums [m][d][t][e]     16MB
__device__ uint4 g_WF[15 * 1024];          // W fragments [u*3+l][(ks*8+nt)*32+lane]

// ---------------- bf16 split helpers ----------------
__device__ __forceinline__ uint32_t pk(unsigned short a, unsigned short b) {
    return (uint32_t)a | ((uint32_t)b << 16);
}
__device__ __forceinline__ void split2(float fx, float fy, uint32_t& h, uint32_t& l) {
    __nv_bfloat16 h0 = __float2bfloat16(fx), h1 = __float2bfloat16(fy);
    h = pk(__bfloat16_as_ushort(h0), __bfloat16_as_ushort(h1));
    l = pk(__bfloat16_as_ushort(__float2bfloat16(fx - __bfloat162float(h0))),
           __bfloat16_as_ushort(__float2bfloat16(fy - __bfloat162float(h1))));
}
__device__ __forceinline__ void mma_bf16(float* d, uint32_t a0, uint32_t a1,
                                         uint32_t a2, uint32_t a3,
                                         uint32_t b0, uint32_t b1) {
    asm volatile(
        "mma.sync.aligned.m16n8k16.row.col.f32.bf16.bf16.f32 "
        "{%0,%1,%2,%3},{%4,%5,%6,%7},{%8,%9},{%0,%1,%2,%3};"
        : "+f"(d[0]), "+f"(d[1]), "+f"(d[2]), "+f"(d[3])
        : "r"(a0), "r"(a1), "r"(a2), "r"(a3), "r"(b0), "r"(b1));
}

#define MLP_SMEM (9216 * 4)   // output staging only (36.9KB)

// ---------------- Kernel 0: precompute W fragments (one block per (u,l)) --
__global__ void __launch_bounds__(256) k_wprep(
    const float* __restrict__ wq_w, const float* __restrict__ wk_w)
{
    const int ul = blockIdx.x;          // 0..14
    const int u = ul / 3, l = ul % 3;
    const float* W = (u == 0) ? wq_w : wk_w + (size_t)(u - 1) * 3 * DD * DD;
    const float* Wlay = W + (size_t)l * DD * DD;

    const int tid = threadIdx.x;
    const int w = tid >> 5, lane = tid & 31;
    const int g = lane >> 2, q = lane & 3;
    const int n = w * 8 + g;

    #pragma unroll
    for (int ks = 0; ks < 4; ks++) {
        const float* wp = Wlay + (ks * 16 + 2 * q) * 64 + n;
        float b00 = wp[0],      b01 = wp[64];
        float b10 = wp[8 * 64], b11 = wp[9 * 64];
        uint4 v;
        split2(b00, b01, v.x, v.z);
        split2(b10, b11, v.y, v.w);
        g_WF[ul * 1024 + (ks * 8 + w) * 32 + lane] = v;
    }
}

// ---------------- Kernel 1: 5 MLPs, register-resident A fragments ---------
// grid (T/128, 5), 256 threads (8 warps); warp w owns rows w*16 .. w*16+15.
// No shared memory except final output staging; no barriers until the end.
__global__ void __launch_bounds__(256, 2) k_mlp(
    const float* __restrict__ X,
    const float* __restrict__ wq_b, const float* __restrict__ wk_b)
{
    extern __shared__ __align__(16) float St[];   // staging [9216]

    const int tid  = threadIdx.x;
    const int w    = tid >> 5;
    const int lane = tid & 31;
    const int g    = lane >> 2;   // 0..7
    const int q    = lane & 3;    // 0..3
    const int u    = blockIdx.y;
    const int base = blockIdx.x * 128;
    const int m_in = (u == 0) ? 0 : (u - 1);
    const float* B = (u == 0) ? wq_b : wk_b + (size_t)(u - 1) * 3 * DD;

    // ---- initial A fragments straight from X into registers ----
    uint4 AH[4], AL[4];
    {
        const int r0 = base + w * 16 + g;
        const float* x0 = X + ((size_t)m_in * TT + r0) * DD;
        const float* x1 = x0 + 8 * DD;
        #pragma unroll
        for (int ks = 0; ks < 4; ks++) {
            float2 a0 = *(const float2*)(x0 + ks * 16 + 2 * q);
            float2 a2 = *(const float2*)(x0 + ks * 16 + 8 + 2 * q);
            float2 a1 = *(const float2*)(x1 + ks * 16 + 2 * q);
            float2 a3 = *(const float2*)(x1 + ks * 16 + 8 + 2 * q);
            if (u >= 1) {
                if (ks == 0 && q == 0) {
                    ((float2*)g_V2)[(size_t)m_in * TT + r0]     = a0;
                    ((float2*)g_V2)[(size_t)m_in * TT + r0 + 8] = a1;
                }
                if (ks == 3 && q == 3) {            // k = 63 lives in a2.y/a3.y
                    g_T2[(size_t)m_in * TT + r0]     = a2.y;
                    g_T2[(size_t)m_in * TT + r0 + 8] = a3.y;
                }
            }
            split2(a0.x, a0.y, AH[ks].x, AL[ks].x);
            split2(a2.x, a2.y, AH[ks].y, AL[ks].y);
            split2(a1.x, a1.y, AH[ks].z, AL[ks].z);
            split2(a3.x, a3.y, AH[ks].w, AL[ks].w);
        }
    }

    #pragma unroll
    for (int l = 0; l < 3; l++) {
        const uint4* wf = g_WF + (u * 3 + l) * 1024;

        float d[8][4];
        #pragma unroll
        for (int nt = 0; nt < 8; nt++)
            #pragma unroll
            for (int j = 0; j < 4; j++) d[nt][j] = 0.0f;

        #pragma unroll
        for (int ks = 0; ks < 4; ks++) {
            #pragma unroll
            for (int nt = 0; nt < 8; nt++) {
                const uint4 b = __ldg(wf + (ks * 8 + nt) * 32 + lane);
                mma_bf16(d[nt], AH[ks].x, AH[ks].z, AH[ks].y, AH[ks].w, b.x, b.y);
                mma_bf16(d[nt], AH[ks].x, AH[ks].z, AH[ks].y, AH[ks].w, b.z, b.w);
                mma_bf16(d[nt], AL[ks].x, AL[ks].z, AL[ks].y, AL[ks].w, b.x, b.y);
            }
        }

        if (l < 2) {
            // ---- epilogue -> next layer's A fragments (registers only) ----
            #pragma unroll
            for (int ksn = 0; ksn < 4; ksn++) {
                const int nt0 = 2 * ksn, nt1 = nt0 + 1;
                const int c0 = nt0 * 8 + 2 * q, c1 = nt1 * 8 + 2 * q;
                float2 b0 = __ldg((const float2*)(B + l * 64 + c0));
                float2 b1 = __ldg((const float2*)(B + l * 64 + c1));
                float f0x = fmaxf(d[nt0][0] + b0.x, 0.0f);
                float f0y = fmaxf(d[nt0][1] + b0.y, 0.0f);
                float f1x = fmaxf(d[nt1][0] + b1.x, 0.0f);
                float f1y = fmaxf(d[nt1][1] + b1.y, 0.0f);
                float f2x = fmaxf(d[nt0][2] + b0.x, 0.0f);
                float f2y = fmaxf(d[nt0][3] + b0.y, 0.0f);
                float f3x = fmaxf(d[nt1][2] + b1.x, 0.0f);
                float f3y = fmaxf(d[nt1][3] + b1.y, 0.0f);
                split2(f0x, f0y, AH[ksn].x, AL[ksn].x);
                split2(f1x, f1y, AH[ksn].y, AL[ksn].y);
                split2(f2x, f2y, AH[ksn].z, AL[ksn].z);
                split2(f3x, f3y, AH[ksn].w, AL[ksn].w);
            }
        } else {
            // ---- final: stage in smem, then coalesced float4 stores ----
            const int row0 = w * 16 + g;
            if (u == 0) {
                #pragma unroll
                for (int nt = 0; nt < 8; nt++) {
                    const int col = nt * 8 + 2 * q;
                    float2 bb = __ldg((const float2*)(B + 128 + col));
                    St[row0 * 72 + col]           = d[nt][0] + bb.x;
                    St[row0 * 72 + col + 1]       = d[nt][1] + bb.y;
                    St[(row0 + 8) * 72 + col]     = d[nt][2] + bb.x;
                    St[(row0 + 8) * 72 + col + 1] = d[nt][3] + bb.y;
                }
                __syncthreads();
                const int row = tid >> 1, c0 = (tid & 1) * 32;
                #pragma unroll
                for (int qq = 0; qq < 8; qq++) {
                    float4 v = *(float4*)&St[row * 72 + c0 + qq * 4];
                    *(float4*)&g_Q[(size_t)(base + row) * 64 + c0 + qq * 4] = v;
                }
            } else {
                #pragma unroll
                for (int nt = 0; nt < 8; nt++) {
                    const int col = nt * 8 + 2 * q;
                    float2 bb = __ldg((const float2*)(B + 128 + col));
                    St[col * 132 + row0]           = d[nt][0] + bb.x;
                    St[(col + 1) * 132 + row0]     = d[nt][1] + bb.y;
                    St[col * 132 + row0 + 8]       = d[nt][2] + bb.x;
                    St[(col + 1) * 132 + row0 + 8] = d[nt][3] + bb.y;
                }
                __syncthreads();
                const int col = tid >> 2, l4 = tid & 3;
                const size_t cb = (size_t)((u - 1) * 64 + col) * TT + base;
                #pragma unroll
                for (int qq = 0; qq < 8; qq++) {
                    const int row = l4 * 4 + qq * 16;
                    float4 v = *(float4*)&St[col * 132 + row];
                    *(float4*)&g_KT[cb + row] = v;
                }
            }
        }
    }
}

// ---------------- Kernel 2: fused scan (blocks 0..511) + searchsorted (512..639)
__global__ void __launch_bounds__(256) k_scanIdx(float* __restrict__ out)
{
    const int tid = threadIdx.x;

    if (blockIdx.x >= 512) {
        const int gid = (blockIdx.x - 512) * 256 + tid;   // [0, MM*TT)
        if (gid < TT)
            ((float2*)out)[gid] = make_float2(0.0f, 0.0f);
        const int t = gid & (TT - 1);
        const int m = gid >> 13;
        const float key = g_T2[t];
        const float* arr = g_T2 + (size_t)m * TT;
        int lo = 0, hi = TT;
        while (lo < hi) {
            int mid = (lo + hi) >> 1;
            if (arr[mid] <= key) lo = mid + 1; else hi = mid;
        }
        g_idx[gid] = lo - 1;
        return;
    }

    const int ch  = blockIdx.x >> 1;      // m*64+d
    const int seg = blockIdx.x & 1;
    const int m   = ch >> 6;

    const float4* kp = (const float4*)(g_KT + (size_t)ch * TT);
    const float4* vp = (const float4*)(g_V2 + (size_t)m * TT * 2);

    float pre0 = 0.0f, pre1 = 0.0f;
    if (seg) {
        const int pi = tid * 16;
        #pragma unroll
        for (int q = 0; q < 4; q++) {
            float4 k4 = kp[(pi >> 2) + q];
            float4 va = vp[(pi >> 1) + q * 2];
            float4 vb = vp[(pi >> 1) + q * 2 + 1];
            pre0 += k4.x * va.x + k4.y * va.z + k4.z * vb.x + k4.w * vb.z;
            pre1 += k4.x * va.y + k4.y * va.w + k4.z * vb.y + k4.w * vb.w;
        }
    }

    const int t0 = seg * SEG + tid * 16;
    float kk[16];
    #pragma unroll
    for (int q = 0; q < 4; q++) {
        float4 k4 = kp[(t0 >> 2) + q];
        kk[q * 4 + 0] = k4.x; kk[q * 4 + 1] = k4.y;
        kk[q * 4 + 2] = k4.z; kk[q * 4 + 3] = k4.w;
    }
    float p0[16], p1[16];
    #pragma unroll
    for (int q = 0; q < 8; q++) {
        float4 v = vp[(t0 >> 1) + q];
        p0[q * 2]     = kk[q * 2]     * v.x;
        p1[q * 2]     = kk[q * 2]     * v.y;
        p0[q * 2 + 1] = kk[q * 2 + 1] * v.z;
        p1[q * 2 + 1] = kk[q * 2 + 1] * v.w;
    }
    #pragma unroll
    for (int e = 1; e < 16; e++) { p0[e] += p0[e - 1]; p1[e] += p1[e - 1]; }

    const int lane = tid & 31, wid = tid >> 5;
    float s0 = p0[15], s1 = p1[15];
    const float t00 = s0, t11 = s1;
    #pragma unroll
    for (int off = 1; off < 32; off <<= 1) {
        float n0 = __shfl_up_sync(0xffffffffu, s0, off);
        float n1 = __shfl_up_sync(0xffffffffu, s1, off);
        if (lane >= off) { s0 += n0; s1 += n1; }
    }
    float pr0 = pre0, pr1 = pre1;
    if (seg) {
        #pragma unroll
        for (int off = 16; off > 0; off >>= 1) {
            pr0 += __shfl_down_sync(0xffffffffu, pr0, off);
            pr1 += __shfl_down_sync(0xffffffffu, pr1, off);
        }
    }
    __shared__ float ws0[8], ws1[8], wp0[8], wp1[8];
    if (lane == 31) { ws0[wid] = s0; ws1[wid] = s1; }
    if (lane == 0)  { wp0[wid] = pr0; wp1[wid] = pr1; }
    __syncthreads();
    float base0 = 0.0f, base1 = 0.0f;
    #pragma unroll
    for (int w = 0; w < 8; w++) {
        base0 += wp0[w]; base1 += wp1[w];
        if (w < wid) { base0 += ws0[w]; base1 += ws1[w]; }
    }
    base0 += s0 - t00;
    base1 += s1 - t11;

    float4* sp = (float4*)(g_S + (size_t)ch * TT * 2);
    #pragma unroll
    for (int q = 0; q < 8; q++) {
        float4 o;
        o.x = base0 + p0[q * 2];     o.y = base1 + p1[q * 2];
        o.z = base0 + p0[q * 2 + 1]; o.w = base1 + p1[q * 2 + 1];
        sp[(t0 >> 1) + q] = o;
    }
}

// ---------------- Kernel 3: gather + contract + atomic accumulate ---------
__global__ void __launch_bounds__(256) k_gath(float* __restrict__ out)
{
    __shared__ float Qs[64 * 65];
    __shared__ float2 red[256];

    const int m   = blockIdx.y;
    const int t0  = blockIdx.x * 64;
    const int tid = threadIdx.x;
    const int lt  = tid & 63;
    const int dq  = tid >> 6;

    {
        const int r = tid >> 2, c4 = tid & 3;
        const float4* src = (const float4*)(g_Q + (size_t)(t0 + r) * 64 + c4 * 16);
        #pragma unroll
        for (int q = 0; q < 4; q++) {
            float4 v = src[q];
            int d0 = c4 * 16 + q * 4;
            Qs[r * 65 + d0 + 0] = v.x;
            Qs[r * 65 + d0 + 1] = v.y;
            Qs[r * 65 + d0 + 2] = v.z;
            Qs[r * 65 + d0 + 3] = v.w;
        }
    }

    const int idx = g_idx[(size_t)m * TT + t0 + lt];
    __syncthreads();

    float a0 = 0.0f, a1 = 0.0f;
    if (idx >= 0) {
        const float2* sp = (const float2*)g_S + (size_t)(m * 64 + dq * 16) * TT + idx;
        #pragma unroll
        for (int dd = 0; dd < 16; dd++) {
            float q  = Qs[lt * 65 + dq * 16 + dd];
            float2 s = sp[(size_t)dd * TT];
            a0 += q * s.x;
            a1 += q * s.y;
        }
    }
    red[tid] = make_float2(a0, a1);
    __syncthreads();

    if (dq == 0) {
        float ax = 0.0f, ay = 0.0f;
        #pragma unroll
        for (int q = 0; q < 4; q++) {
            float2 v = red[lt + 64 * q];
            ax += v.x; ay += v.y;
        }
        atomicAdd(out + (size_t)(t0 + lt) * 2 + 0, ax);
        atomicAdd(out + (size_t)(t0 + lt) * 2 + 1, ay);
    }
}

// ---------------- launch ----------------
extern "C" void kernel_launch(void* const* d_in, const int* in_sizes, int n_in,
                              void* d_out, int out_size)
{
    const float* X    = (const float*)d_in[0];
    const float* wq_w = (const float*)d_in[1];
    const float* wq_b = (const float*)d_in[2];
    const float* wk_w = (const float*)d_in[3];
    const float* wk_b = (const float*)d_in[4];
    float* out = (float*)d_out;

    k_wprep  <<<15, 256>>>(wq_w, wk_w);
    k_mlp    <<<dim3(TT / 128, 5), 256, MLP_SMEM>>>(X, wq_b, wk_b);
    k_scanIdx<<<512 + 128, 256>>>(out);
    k_gath   <<<dim3(TT / 64, MM), 256>>>(out);
}

// round 14
// speedup vs baseline: 1.1112x; 1.0218x over previous
#include <cuda_runtime.h>
#include <cuda_bf16.h>
#include <cstdint>

#define TT 8192
#define DD 64
#define MM 4
#define SEG 4096

// ---------------- scratch (device globals; no allocation) ----------------
__device__ float g_Q [TT * DD];            // Q row-major [t][d]           2MB
__device__ float g_KT[MM * DD * TT];       // K transposed [m][d][t]       8MB
__device__ float g_V2[MM * TT * 2];        // V interleaved [m][t][e]      256KB
__device__ float g_T2[MM * TT];            // t2 per modality (t1 = m=0)
__device__ int   g_idx[MM * TT];           // searchsorted results
__device__ float g_S [MM * DD * TT * 2];   // prefix sums [m][d][t][e]     16MB
__device__ uint4 g_WF[15 * 1024];          // W fragments [u*3+l][(ks*8+nt)*32+lane]

// ---------------- bf16 split helpers ----------------
__device__ __forceinline__ uint32_t pk(unsigned short a, unsigned short b) {
    return (uint32_t)a | ((uint32_t)b << 16);
}
__device__ __forceinline__ void split2(float fx, float fy, uint32_t& h, uint32_t& l) {
    __nv_bfloat16 h0 = __float2bfloat16(fx), h1 = __float2bfloat16(fy);
    h = pk(__bfloat16_as_ushort(h0), __bfloat16_as_ushort(h1));
    l = pk(__bfloat16_as_ushort(__float2bfloat16(fx - __bfloat162float(h0))),
           __bfloat16_as_ushort(__float2bfloat16(fy - __bfloat162float(h1))));
}
__device__ __forceinline__ void mma_bf16(float* d, uint32_t a0, uint32_t a1,
                                         uint32_t a2, uint32_t a3,
                                         uint32_t b0, uint32_t b1) {
    asm volatile(
        "mma.sync.aligned.m16n8k16.row.col.f32.bf16.bf16.f32 "
        "{%0,%1,%2,%3},{%4,%5,%6,%7},{%8,%9},{%0,%1,%2,%3};"
        : "+f"(d[0]), "+f"(d[1]), "+f"(d[2]), "+f"(d[3])
        : "r"(a0), "r"(a1), "r"(a2), "r"(a3), "r"(b0), "r"(b1));
}

#define MLP_SMEM (9216 * 4)   // output staging only (36.9KB)

// ---------------- Kernel 0: precompute W fragments (one block per (u,l)) --
__global__ void __launch_bounds__(256) k_wprep(
    const float* __restrict__ wq_w, const float* __restrict__ wk_w)
{
    const int ul = blockIdx.x;          // 0..14
    const int u = ul / 3, l = ul % 3;
    const float* W = (u == 0) ? wq_w : wk_w + (size_t)(u - 1) * 3 * DD * DD;
    const float* Wlay = W + (size_t)l * DD * DD;

    const int tid = threadIdx.x;
    const int w = tid >> 5, lane = tid & 31;
    const int g = lane >> 2, q = lane & 3;
    const int n = w * 8 + g;

    #pragma unroll
    for (int ks = 0; ks < 4; ks++) {
        const float* wp = Wlay + (ks * 16 + 2 * q) * 64 + n;
        float b00 = wp[0],      b01 = wp[64];
        float b10 = wp[8 * 64], b11 = wp[9 * 64];
        uint4 v;
        split2(b00, b01, v.x, v.z);
        split2(b10, b11, v.y, v.w);
        g_WF[ul * 1024 + (ks * 8 + w) * 32 + lane] = v;
    }
}

// ---------------- Kernel 1: 5 MLPs, register-resident A fragments ---------
__global__ void __launch_bounds__(256, 2) k_mlp(
    const float* __restrict__ X,
    const float* __restrict__ wq_b, const float* __restrict__ wk_b)
{
    extern __shared__ __align__(16) float St[];   // staging [9216]

    const int tid  = threadIdx.x;
    const int w    = tid >> 5;
    const int lane = tid & 31;
    const int g    = lane >> 2;   // 0..7
    const int q    = lane & 3;    // 0..3
    const int u    = blockIdx.y;
    const int base = blockIdx.x * 128;
    const int m_in = (u == 0) ? 0 : (u - 1);
    const float* B = (u == 0) ? wq_b : wk_b + (size_t)(u - 1) * 3 * DD;

    uint4 AH[4], AL[4];
    {
        const int r0 = base + w * 16 + g;
        const float* x0 = X + ((size_t)m_in * TT + r0) * DD;
        const float* x1 = x0 + 8 * DD;
        #pragma unroll
        for (int ks = 0; ks < 4; ks++) {
            float2 a0 = *(const float2*)(x0 + ks * 16 + 2 * q);
            float2 a2 = *(const float2*)(x0 + ks * 16 + 8 + 2 * q);
            float2 a1 = *(const float2*)(x1 + ks * 16 + 2 * q);
            float2 a3 = *(const float2*)(x1 + ks * 16 + 8 + 2 * q);
            if (u >= 1) {
                if (ks == 0 && q == 0) {
                    ((float2*)g_V2)[(size_t)m_in * TT + r0]     = a0;
                    ((float2*)g_V2)[(size_t)m_in * TT + r0 + 8] = a1;
                }
                if (ks == 3 && q == 3) {
                    g_T2[(size_t)m_in * TT + r0]     = a2.y;
                    g_T2[(size_t)m_in * TT + r0 + 8] = a3.y;
                }
            }
            split2(a0.x, a0.y, AH[ks].x, AL[ks].x);
            split2(a2.x, a2.y, AH[ks].y, AL[ks].y);
            split2(a1.x, a1.y, AH[ks].z, AL[ks].z);
            split2(a3.x, a3.y, AH[ks].w, AL[ks].w);
        }
    }

    #pragma unroll
    for (int l = 0; l < 3; l++) {
        const uint4* wf = g_WF + (u * 3 + l) * 1024;

        float d[8][4];
        #pragma unroll
        for (int nt = 0; nt < 8; nt++)
            #pragma unroll
            for (int j = 0; j < 4; j++) d[nt][j] = 0.0f;

        #pragma unroll
        for (int ks = 0; ks < 4; ks++) {
            #pragma unroll
            for (int nt = 0; nt < 8; nt++) {
                const uint4 b = __ldg(wf + (ks * 8 + nt) * 32 + lane);
                mma_bf16(d[nt], AH[ks].x, AH[ks].z, AH[ks].y, AH[ks].w, b.x, b.y);
                mma_bf16(d[nt], AH[ks].x, AH[ks].z, AH[ks].y, AH[ks].w, b.z, b.w);
                mma_bf16(d[nt], AL[ks].x, AL[ks].z, AL[ks].y, AL[ks].w, b.x, b.y);
            }
        }

        if (l < 2) {
            #pragma unroll
            for (int ksn = 0; ksn < 4; ksn++) {
                const int nt0 = 2 * ksn, nt1 = nt0 + 1;
                const int c0 = nt0 * 8 + 2 * q, c1 = nt1 * 8 + 2 * q;
                float2 b0 = __ldg((const float2*)(B + l * 64 + c0));
                float2 b1 = __ldg((const float2*)(B + l * 64 + c1));
                float f0x = fmaxf(d[nt0][0] + b0.x, 0.0f);
                float f0y = fmaxf(d[nt0][1] + b0.y, 0.0f);
                float f1x = fmaxf(d[nt1][0] + b1.x, 0.0f);
                float f1y = fmaxf(d[nt1][1] + b1.y, 0.0f);
                float f2x = fmaxf(d[nt0][2] + b0.x, 0.0f);
                float f2y = fmaxf(d[nt0][3] + b0.y, 0.0f);
                float f3x = fmaxf(d[nt1][2] + b1.x, 0.0f);
                float f3y = fmaxf(d[nt1][3] + b1.y, 0.0f);
                split2(f0x, f0y, AH[ksn].x, AL[ksn].x);
                split2(f1x, f1y, AH[ksn].y, AL[ksn].y);
                split2(f2x, f2y, AH[ksn].z, AL[ksn].z);
                split2(f3x, f3y, AH[ksn].w, AL[ksn].w);
            }
        } else {
            const int row0 = w * 16 + g;
            if (u == 0) {
                #pragma unroll
                for (int nt = 0; nt < 8; nt++) {
                    const int col = nt * 8 + 2 * q;
                    float2 bb = __ldg((const float2*)(B + 128 + col));
                    St[row0 * 72 + col]           = d[nt][0] + bb.x;
                    St[row0 * 72 + col + 1]       = d[nt][1] + bb.y;
                    St[(row0 + 8) * 72 + col]     = d[nt][2] + bb.x;
                    St[(row0 + 8) * 72 + col + 1] = d[nt][3] + bb.y;
                }
                __syncthreads();
                const int row = tid >> 1, c0 = (tid & 1) * 32;
                #pragma unroll
                for (int qq = 0; qq < 8; qq++) {
                    float4 v = *(float4*)&St[row * 72 + c0 + qq * 4];
                    *(float4*)&g_Q[(size_t)(base + row) * 64 + c0 + qq * 4] = v;
                }
            } else {
                #pragma unroll
                for (int nt = 0; nt < 8; nt++) {
                    const int col = nt * 8 + 2 * q;
                    float2 bb = __ldg((const float2*)(B + 128 + col));
                    St[col * 132 + row0]           = d[nt][0] + bb.x;
                    St[(col + 1) * 132 + row0]     = d[nt][1] + bb.y;
                    St[col * 132 + row0 + 8]       = d[nt][2] + bb.x;
                    St[(col + 1) * 132 + row0 + 8] = d[nt][3] + bb.y;
                }
                __syncthreads();
                const int col = tid >> 2, l4 = tid & 3;
                const size_t cb = (size_t)((u - 1) * 64 + col) * TT + base;
                #pragma unroll
                for (int qq = 0; qq < 8; qq++) {
                    const int row = l4 * 4 + qq * 16;
                    float4 v = *(float4*)&St[col * 132 + row];
                    *(float4*)&g_KT[cb + row] = v;
                }
            }
        }
    }
}

// ---------------- Kernel 2: fused scan (blocks 0..511) + searchsorted (512..639)
__global__ void __launch_bounds__(256) k_scanIdx(float* __restrict__ out)
{
    const int tid = threadIdx.x;

    if (blockIdx.x >= 512) {
        const int gid = (blockIdx.x - 512) * 256 + tid;   // [0, MM*TT)
        if (gid < TT)
            ((float2*)out)[gid] = make_float2(0.0f, 0.0f);
        const int t = gid & (TT - 1);
        const int m = gid >> 13;
        const float key = g_T2[t];
        const float* arr = g_T2 + (size_t)m * TT;
        int lo = 0, hi = TT;
        while (lo < hi) {
            int mid = (lo + hi) >> 1;
            if (arr[mid] <= key) lo = mid + 1; else hi = mid;
        }
        g_idx[gid] = lo - 1;
        return;
    }

    const int ch  = blockIdx.x >> 1;      // m*64+d
    const int seg = blockIdx.x & 1;
    const int m   = ch >> 6;

    const float4* kp = (const float4*)(g_KT + (size_t)ch * TT);
    const float4* vp = (const float4*)(g_V2 + (size_t)m * TT * 2);

    float pre0 = 0.0f, pre1 = 0.0f;
    if (seg) {
        const int pi = tid * 16;
        #pragma unroll
        for (int q = 0; q < 4; q++) {
            float4 k4 = kp[(pi >> 2) + q];
            float4 va = vp[(pi >> 1) + q * 2];
            float4 vb = vp[(pi >> 1) + q * 2 + 1];
            pre0 += k4.x * va.x + k4.y * va.z + k4.z * vb.x + k4.w * vb.z;
            pre1 += k4.x * va.y + k4.y * va.w + k4.z * vb.y + k4.w * vb.w;
        }
    }

    const int t0 = seg * SEG + tid * 16;
    float kk[16];
    #pragma unroll
    for (int q = 0; q < 4; q++) {
        float4 k4 = kp[(t0 >> 2) + q];
        kk[q * 4 + 0] = k4.x; kk[q * 4 + 1] = k4.y;
        kk[q * 4 + 2] = k4.z; kk[q * 4 + 3] = k4.w;
    }
    float p0[16], p1[16];
    #pragma unroll
    for (int q = 0; q < 8; q++) {
        float4 v = vp[(t0 >> 1) + q];
        p0[q * 2]     = kk[q * 2]     * v.x;
        p1[q * 2]     = kk[q * 2]     * v.y;
        p0[q * 2 + 1] = kk[q * 2 + 1] * v.z;
        p1[q * 2 + 1] = kk[q * 2 + 1] * v.w;
    }
    #pragma unroll
    for (int e = 1; e < 16; e++) { p0[e] += p0[e - 1]; p1[e] += p1[e - 1]; }

    const int lane = tid & 31, wid = tid >> 5;
    float s0 = p0[15], s1 = p1[15];
    const float t00 = s0, t11 = s1;
    #pragma unroll
    for (int off = 1; off < 32; off <<= 1) {
        float n0 = __shfl_up_sync(0xffffffffu, s0, off);
        float n1 = __shfl_up_sync(0xffffffffu, s1, off);
        if (lane >= off) { s0 += n0; s1 += n1; }
    }
    float pr0 = pre0, pr1 = pre1;
    if (seg) {
        #pragma unroll
        for (int off = 16; off > 0; off >>= 1) {
            pr0 += __shfl_down_sync(0xffffffffu, pr0, off);
            pr1 += __shfl_down_sync(0xffffffffu, pr1, off);
        }
    }
    __shared__ float ws0[8], ws1[8], wp0[8], wp1[8];
    if (lane == 31) { ws0[wid] = s0; ws1[wid] = s1; }
    if (lane == 0)  { wp0[wid] = pr0; wp1[wid] = pr1; }
    __syncthreads();
    float base0 = 0.0f, base1 = 0.0f;
    #pragma unroll
    for (int w = 0; w < 8; w++) {
        base0 += wp0[w]; base1 += wp1[w];
        if (w < wid) { base0 += ws0[w]; base1 += ws1[w]; }
    }
    base0 += s0 - t00;
    base1 += s1 - t11;

    float4* sp = (float4*)(g_S + (size_t)ch * TT * 2);
    #pragma unroll
    for (int q = 0; q < 8; q++) {
        float4 o;
        o.x = base0 + p0[q * 2];     o.y = base1 + p1[q * 2];
        o.z = base0 + p0[q * 2 + 1]; o.w = base1 + p1[q * 2 + 1];
        sp[(t0 >> 1) + q] = o;
    }
}

// ---------------- Kernel 3: gather + contract + atomic accumulate ---------
// grid (T/64, M*2): blockIdx.y = m*2 + dhalf. 256 threads = (lt 0..63, dq 0..3),
// thread covers 8 d's: d = dhalf*32 + dq*8 + dd.
__global__ void __launch_bounds__(256) k_gath(float* __restrict__ out)
{
    __shared__ float Qs[64 * 33];
    __shared__ float2 red[256];

    const int m   = blockIdx.y >> 1;
    const int dh  = blockIdx.y & 1;
    const int t0  = blockIdx.x * 64;
    const int tid = threadIdx.x;
    const int lt  = tid & 63;
    const int dq  = tid >> 6;

    // load Q tile half [64 t][32 d] (scalar stores, pad 33)
    {
        const int r = tid >> 2, c4 = tid & 3;
        const float* src = g_Q + (size_t)(t0 + r) * 64 + dh * 32 + c4 * 8;
        #pragma unroll
        for (int j = 0; j < 2; j++) {
            float4 v = ((const float4*)src)[j];
            const int c = c4 * 8 + j * 4;
            Qs[r * 33 + c + 0] = v.x;
            Qs[r * 33 + c + 1] = v.y;
            Qs[r * 33 + c + 2] = v.z;
            Qs[r * 33 + c + 3] = v.w;
        }
    }

    const int idx = g_idx[(size_t)m * TT + t0 + lt];
    __syncthreads();

    float a0 = 0.0f, a1 = 0.0f;
    if (idx >= 0) {
        const float2* sp = (const float2*)g_S
            + (size_t)(m * 64 + dh * 32 + dq * 8) * TT + idx;
        #pragma unroll
        for (int dd = 0; dd < 8; dd++) {
            float q  = Qs[lt * 33 + dq * 8 + dd];
            float2 s = sp[(size_t)dd * TT];
            a0 += q * s.x;
            a1 += q * s.y;
        }
    }
    red[tid] = make_float2(a0, a1);
    __syncthreads();

    if (dq == 0) {
        float ax = 0.0f, ay = 0.0f;
        #pragma unroll
        for (int q = 0; q < 4; q++) {
            float2 v = red[lt + 64 * q];
            ax += v.x; ay += v.y;
        }
        atomicAdd(out + (size_t)(t0 + lt) * 2 + 0, ax);
        atomicAdd(out + (size_t)(t0 + lt) * 2 + 1, ay);
    }
}

// ---------------- launch ----------------
extern "C" void kernel_launch(void* const* d_in, const int* in_sizes, int n_in,
                              void* d_out, int out_size)
{
    const float* X    = (const float*)d_in[0];
    const float* wq_w = (const float*)d_in[1];
    const float* wq_b = (const float*)d_in[2];
    const float* wk_w = (const float*)d_in[3];
    const float* wk_b = (const float*)d_in[4];
    float* out = (float*)d_out;

    k_wprep  <<<15, 256>>>(wq_w, wk_w);
    k_mlp    <<<dim3(TT / 128, 5), 256, MLP_SMEM>>>(X, wq_b, wk_b);
    k_scanIdx<<<512 + 128, 256>>>(out);
    k_gath   <<<dim3(TT / 64, MM * 2), 256>>>(out);
}

// round 15
// speedup vs baseline: 1.1342x; 1.0207x over previous
#include <cuda_runtime.h>
#include <cuda_bf16.h>
#include <cstdint>

#define TT 8192
#define DD 64
#define MM 4
#define SEG 4096

// ---------------- scratch (device globals; no allocation) ----------------
__device__ float g_Q [TT * DD];            // Q row-major [t][d]           2MB
__device__ float g_KT[MM * DD * TT];       // K transposed [m][d][t]       8MB
__device__ float g_V2[MM * TT * 2];        // V interleaved [m][t][e]      256KB
__device__ float g_T2[MM * TT];            // t2 per modality (t1 = m=0)
__device__ int   g_idx[MM * TT];           // searchsorted results
__device__ float g_S [MM * DD * TT * 2];   // prefix sums [m][d][t][e]     16MB
__device__ uint4 g_WF[15 * 1024];          // W fragments [u*3+l][(ks*8+nt)*32+lane]

// ---------------- bf16 split helpers ----------------
__device__ __forceinline__ uint32_t pk(unsigned short a, unsigned short b) {
    return (uint32_t)a | ((uint32_t)b << 16);
}
__device__ __forceinline__ void split2(float fx, float fy, uint32_t& h, uint32_t& l) {
    __nv_bfloat16 h0 = __float2bfloat16(fx), h1 = __float2bfloat16(fy);
    h = pk(__bfloat16_as_ushort(h0), __bfloat16_as_ushort(h1));
    l = pk(__bfloat16_as_ushort(__float2bfloat16(fx - __bfloat162float(h0))),
           __bfloat16_as_ushort(__float2bfloat16(fy - __bfloat162float(h1))));
}
__device__ __forceinline__ void mma_bf16(float* d, uint32_t a0, uint32_t a1,
                                         uint32_t a2, uint32_t a3,
                                         uint32_t b0, uint32_t b1) {
    asm volatile(
        "mma.sync.aligned.m16n8k16.row.col.f32.bf16.bf16.f32 "
        "{%0,%1,%2,%3},{%4,%5,%6,%7},{%8,%9},{%0,%1,%2,%3};"
        : "+f"(d[0]), "+f"(d[1]), "+f"(d[2]), "+f"(d[3])
        : "r"(a0), "r"(a1), "r"(a2), "r"(a3), "r"(b0), "r"(b1));
}

#define MLP_SMEM (4608 * 4)   // output staging only (18.4KB)

// ---------------- Kernel 0: precompute W fragments (one block per (u,l)) --
__global__ void __launch_bounds__(256) k_wprep(
    const float* __restrict__ wq_w, const float* __restrict__ wk_w)
{
    const int ul = blockIdx.x;          // 0..14
    const int u = ul / 3, l = ul % 3;
    const float* W = (u == 0) ? wq_w : wk_w + (size_t)(u - 1) * 3 * DD * DD;
    const float* Wlay = W + (size_t)l * DD * DD;

    const int tid = threadIdx.x;
    const int w = tid >> 5, lane = tid & 31;
    const int g = lane >> 2, q = lane & 3;
    const int n = w * 8 + g;

    #pragma unroll
    for (int ks = 0; ks < 4; ks++) {
        const float* wp = Wlay + (ks * 16 + 2 * q) * 64 + n;
        float b00 = wp[0],      b01 = wp[64];
        float b10 = wp[8 * 64], b11 = wp[9 * 64];
        uint4 v;
        split2(b00, b01, v.x, v.z);
        split2(b10, b11, v.y, v.w);
        g_WF[ul * 1024 + (ks * 8 + w) * 32 + lane] = v;
    }
}

// ---------------- Kernel 1: 5 MLPs, 64-row tiles, register-resident A -----
// grid (T/64, 5), 128 threads (4 warps); warp w owns rows w*16 .. w*16+15.
__global__ void __launch_bounds__(128, 4) k_mlp(
    const float* __restrict__ X,
    const float* __restrict__ wq_b, const float* __restrict__ wk_b)
{
    extern __shared__ __align__(16) float St[];   // staging [4608]

    const int tid  = threadIdx.x;
    const int w    = tid >> 5;
    const int lane = tid & 31;
    const int g    = lane >> 2;   // 0..7
    const int q    = lane & 3;    // 0..3
    const int u    = blockIdx.y;
    const int base = blockIdx.x * 64;
    const int m_in = (u == 0) ? 0 : (u - 1);
    const float* B = (u == 0) ? wq_b : wk_b + (size_t)(u - 1) * 3 * DD;

    uint4 AH[4], AL[4];
    {
        const int r0 = base + w * 16 + g;
        const float* x0 = X + ((size_t)m_in * TT + r0) * DD;
        const float* x1 = x0 + 8 * DD;
        #pragma unroll
        for (int ks = 0; ks < 4; ks++) {
            float2 a0 = *(const float2*)(x0 + ks * 16 + 2 * q);
            float2 a2 = *(const float2*)(x0 + ks * 16 + 8 + 2 * q);
            float2 a1 = *(const float2*)(x1 + ks * 16 + 2 * q);
            float2 a3 = *(const float2*)(x1 + ks * 16 + 8 + 2 * q);
            if (u >= 1) {
                if (ks == 0 && q == 0) {
                    ((float2*)g_V2)[(size_t)m_in * TT + r0]     = a0;
                    ((float2*)g_V2)[(size_t)m_in * TT + r0 + 8] = a1;
                }
                if (ks == 3 && q == 3) {
                    g_T2[(size_t)m_in * TT + r0]     = a2.y;
                    g_T2[(size_t)m_in * TT + r0 + 8] = a3.y;
                }
            }
            split2(a0.x, a0.y, AH[ks].x, AL[ks].x);
            split2(a2.x, a2.y, AH[ks].y, AL[ks].y);
            split2(a1.x, a1.y, AH[ks].z, AL[ks].z);
            split2(a3.x, a3.y, AH[ks].w, AL[ks].w);
        }
    }

    #pragma unroll
    for (int l = 0; l < 3; l++) {
        const uint4* wf = g_WF + (u * 3 + l) * 1024;

        float d[8][4];
        #pragma unroll
        for (int nt = 0; nt < 8; nt++)
            #pragma unroll
            for (int j = 0; j < 4; j++) d[nt][j] = 0.0f;

        #pragma unroll
        for (int ks = 0; ks < 4; ks++) {
            #pragma unroll
            for (int nt = 0; nt < 8; nt++) {
                const uint4 b = __ldg(wf + (ks * 8 + nt) * 32 + lane);
                mma_bf16(d[nt], AH[ks].x, AH[ks].z, AH[ks].y, AH[ks].w, b.x, b.y);
                mma_bf16(d[nt], AH[ks].x, AH[ks].z, AH[ks].y, AH[ks].w, b.z, b.w);
                mma_bf16(d[nt], AL[ks].x, AL[ks].z, AL[ks].y, AL[ks].w, b.x, b.y);
            }
        }

        if (l < 2) {
            #pragma unroll
            for (int ksn = 0; ksn < 4; ksn++) {
                const int nt0 = 2 * ksn, nt1 = nt0 + 1;
                const int c0 = nt0 * 8 + 2 * q, c1 = nt1 * 8 + 2 * q;
                float2 b0 = __ldg((const float2*)(B + l * 64 + c0));
                float2 b1 = __ldg((const float2*)(B + l * 64 + c1));
                float f0x = fmaxf(d[nt0][0] + b0.x, 0.0f);
                float f0y = fmaxf(d[nt0][1] + b0.y, 0.0f);
                float f1x = fmaxf(d[nt1][0] + b1.x, 0.0f);
                float f1y = fmaxf(d[nt1][1] + b1.y, 0.0f);
                float f2x = fmaxf(d[nt0][2] + b0.x, 0.0f);
                float f2y = fmaxf(d[nt0][3] + b0.y, 0.0f);
                float f3x = fmaxf(d[nt1][2] + b1.x, 0.0f);
                float f3y = fmaxf(d[nt1][3] + b1.y, 0.0f);
                split2(f0x, f0y, AH[ksn].x, AL[ksn].x);
                split2(f1x, f1y, AH[ksn].y, AL[ksn].y);
                split2(f2x, f2y, AH[ksn].z, AL[ksn].z);
                split2(f3x, f3y, AH[ksn].w, AL[ksn].w);
            }
        } else {
            const int row0 = w * 16 + g;   // 0..63
            if (u == 0) {
                #pragma unroll
                for (int nt = 0; nt < 8; nt++) {
                    const int col = nt * 8 + 2 * q;
                    float2 bb = __ldg((const float2*)(B + 128 + col));
                    St[row0 * 72 + col]           = d[nt][0] + bb.x;
                    St[row0 * 72 + col + 1]       = d[nt][1] + bb.y;
                    St[(row0 + 8) * 72 + col]     = d[nt][2] + bb.x;
                    St[(row0 + 8) * 72 + col + 1] = d[nt][3] + bb.y;
                }
                __syncthreads();
                const int row = tid >> 1, c0 = (tid & 1) * 32;
                #pragma unroll
                for (int qq = 0; qq < 8; qq++) {
                    float4 v = *(float4*)&St[row * 72 + c0 + qq * 4];
                    *(float4*)&g_Q[(size_t)(base + row) * 64 + c0 + qq * 4] = v;
                }
            } else {
                #pragma unroll
                for (int nt = 0; nt < 8; nt++) {
                    const int col = nt * 8 + 2 * q;
                    float2 bb = __ldg((const float2*)(B + 128 + col));
                    St[col * 68 + row0]           = d[nt][0] + bb.x;
                    St[(col + 1) * 68 + row0]     = d[nt][1] + bb.y;
                    St[col * 68 + row0 + 8]       = d[nt][2] + bb.x;
                    St[(col + 1) * 68 + row0 + 8] = d[nt][3] + bb.y;
                }
                __syncthreads();
                const int col = tid >> 1, l2 = tid & 1;
                const size_t cb = (size_t)((u - 1) * 64 + col) * TT + base;
                #pragma unroll
                for (int qq = 0; qq < 8; qq++) {
                    const int row = l2 * 4 + qq * 8;
                    float4 v = *(float4*)&St[col * 68 + row];
                    *(float4*)&g_KT[cb + row] = v;
                }
            }
        }
    }
}

// ---------------- Kernel 2: fused scan (blocks 0..511) + searchsorted (512..639)
__global__ void __launch_bounds__(256) k_scanIdx(float* __restrict__ out)
{
    const int tid = threadIdx.x;

    if (blockIdx.x >= 512) {
        const int gid = (blockIdx.x - 512) * 256 + tid;   // [0, MM*TT)
        if (gid < TT)
            ((float2*)out)[gid] = make_float2(0.0f, 0.0f);
        const int t = gid & (TT - 1);
        const int m = gid >> 13;
        const float key = g_T2[t];
        const float* arr = g_T2 + (size_t)m * TT;
        int lo = 0, hi = TT;
        while (lo < hi) {
            int mid = (lo + hi) >> 1;
            if (arr[mid] <= key) lo = mid + 1; else hi = mid;
        }
        g_idx[gid] = lo - 1;
        return;
    }

    const int ch  = blockIdx.x >> 1;      // m*64+d
    const int seg = blockIdx.x & 1;
    const int m   = ch >> 6;

    const float4* kp = (const float4*)(g_KT + (size_t)ch * TT);
    const float4* vp = (const float4*)(g_V2 + (size_t)m * TT * 2);

    float pre0 = 0.0f, pre1 = 0.0f;
    if (seg) {
        const int pi = tid * 16;
        #pragma unroll
        for (int q = 0; q < 4; q++) {
            float4 k4 = kp[(pi >> 2) + q];
            float4 va = vp[(pi >> 1) + q * 2];
            float4 vb = vp[(pi >> 1) + q * 2 + 1];
            pre0 += k4.x * va.x + k4.y * va.z + k4.z * vb.x + k4.w * vb.z;
            pre1 += k4.x * va.y + k4.y * va.w + k4.z * vb.y + k4.w * vb.w;
        }
    }

    const int t0 = seg * SEG + tid * 16;
    float kk[16];
    #pragma unroll
    for (int q = 0; q < 4; q++) {
        float4 k4 = kp[(t0 >> 2) + q];
        kk[q * 4 + 0] = k4.x; kk[q * 4 + 1] = k4.y;
        kk[q * 4 + 2] = k4.z; kk[q * 4 + 3] = k4.w;
    }
    float p0[16], p1[16];
    #pragma unroll
    for (int q = 0; q < 8; q++) {
        float4 v = vp[(t0 >> 1) + q];
        p0[q * 2]     = kk[q * 2]     * v.x;
        p1[q * 2]     = kk[q * 2]     * v.y;
        p0[q * 2 + 1] = kk[q * 2 + 1] * v.z;
        p1[q * 2 + 1] = kk[q * 2 + 1] * v.w;
    }
    #pragma unroll
    for (int e = 1; e < 16; e++) { p0[e] += p0[e - 1]; p1[e] += p1[e - 1]; }

    const int lane = tid & 31, wid = tid >> 5;
    float s0 = p0[15], s1 = p1[15];
    const float t00 = s0, t11 = s1;
    #pragma unroll
    for (int off = 1; off < 32; off <<= 1) {
        float n0 = __shfl_up_sync(0xffffffffu, s0, off);
        float n1 = __shfl_up_sync(0xffffffffu, s1, off);
        if (lane >= off) { s0 += n0; s1 += n1; }
    }
    float pr0 = pre0, pr1 = pre1;
    if (seg) {
        #pragma unroll
        for (int off = 16; off > 0; off >>= 1) {
            pr0 += __shfl_down_sync(0xffffffffu, pr0, off);
            pr1 += __shfl_down_sync(0xffffffffu, pr1, off);
        }
    }
    __shared__ float ws0[8], ws1[8], wp0[8], wp1[8];
    if (lane == 31) { ws0[wid] = s0; ws1[wid] = s1; }
    if (lane == 0)  { wp0[wid] = pr0; wp1[wid] = pr1; }
    __syncthreads();
    float base0 = 0.0f, base1 = 0.0f;
    #pragma unroll
    for (int w = 0; w < 8; w++) {
        base0 += wp0[w]; base1 += wp1[w];
        if (w < wid) { base0 += ws0[w]; base1 += ws1[w]; }
    }
    base0 += s0 - t00;
    base1 += s1 - t11;

    float4* sp = (float4*)(g_S + (size_t)ch * TT * 2);
    #pragma unroll
    for (int q = 0; q < 8; q++) {
        float4 o;
        o.x = base0 + p0[q * 2];     o.y = base1 + p1[q * 2];
        o.z = base0 + p0[q * 2 + 1]; o.w = base1 + p1[q * 2 + 1];
        sp[(t0 >> 1) + q] = o;
    }
}

// ---------------- Kernel 3: gather + contract + atomic accumulate ---------
// grid (T/64, M*2): blockIdx.y = m*2 + dhalf.
__global__ void __launch_bounds__(256) k_gath(float* __restrict__ out)
{
    __shared__ float Qs[64 * 33];
    __shared__ float2 red[256];

    const int m   = blockIdx.y >> 1;
    const int dh  = blockIdx.y & 1;
    const int t0  = blockIdx.x * 64;
    const int tid = threadIdx.x;
    const int lt  = tid & 63;
    const int dq  = tid >> 6;

    {
        const int r = tid >> 2, c4 = tid & 3;
        const float* src = g_Q + (size_t)(t0 + r) * 64 + dh * 32 + c4 * 8;
        #pragma unroll
        for (int j = 0; j < 2; j++) {
            float4 v = ((const float4*)src)[j];
            const int c = c4 * 8 + j * 4;
            Qs[r * 33 + c + 0] = v.x;
            Qs[r * 33 + c + 1] = v.y;
            Qs[r * 33 + c + 2] = v.z;
            Qs[r * 33 + c + 3] = v.w;
        }
    }

    const int idx = g_idx[(size_t)m * TT + t0 + lt];
    __syncthreads();

    float a0 = 0.0f, a1 = 0.0f;
    if (idx >= 0) {
        const float2* sp = (const float2*)g_S
            + (size_t)(m * 64 + dh * 32 + dq * 8) * TT + idx;
        #pragma unroll
        for (int dd = 0; dd < 8; dd++) {
            float q  = Qs[lt * 33 + dq * 8 + dd];
            float2 s = sp[(size_t)dd * TT];
            a0 += q * s.x;
            a1 += q * s.y;
        }
    }
    red[tid] = make_float2(a0, a1);
    __syncthreads();

    if (dq == 0) {
        float ax = 0.0f, ay = 0.0f;
        #pragma unroll
        for (int q = 0; q < 4; q++) {
            float2 v = red[lt + 64 * q];
            ax += v.x; ay += v.y;
        }
        atomicAdd(out + (size_t)(t0 + lt) * 2 + 0, ax);
        atomicAdd(out + (size_t)(t0 + lt) * 2 + 1, ay);
    }
}

// ---------------- launch ----------------
extern "C" void kernel_launch(void* const* d_in, const int* in_sizes, int n_in,
                              void* d_out, int out_size)
{
    const float* X    = (const float*)d_in[0];
    const float* wq_w = (const float*)d_in[1];
    const float* wq_b = (const float*)d_in[2];
    const float* wk_w = (const float*)d_in[3];
    const float* wk_b = (const float*)d_in[4];
    float* out = (float*)d_out;

    k_wprep  <<<15, 256>>>(wq_w, wk_w);
    k_mlp    <<<dim3(TT / 64, 5), 128, MLP_SMEM>>>(X, wq_b, wk_b);
    k_scanIdx<<<512 + 128, 256>>>(out);
    k_gath   <<<dim3(TT / 64, MM * 2), 256>>>(out);
}

// round 16
// speedup vs baseline: 1.2684x; 1.1184x over previous
#include <cuda_runtime.h>
#include <cuda_bf16.h>
#include <cstdint>

#define TT 8192
#define DD 64
#define MM 4
#define SEG 4096

// ---------------- scratch (device globals; no allocation) ----------------
__device__ float g_Q [TT * DD];            // Q row-major [t][d]           2MB
__device__ float g_KT[MM * DD * TT];       // K transposed [m][d][t]       8MB
__device__ float g_V2[MM * TT * 2];        // V interleaved [m][t][e]      256KB
__device__ float g_T2[MM * TT];            // t2 per modality (t1 = m=0)
__device__ int   g_idx[MM * TT];           // searchsorted results
__device__ float g_S [MM * DD * TT * 2];   // prefix sums [m][d][t][e]     16MB
__device__ uint4 g_WF[15 * 1024];          // W fragments [u*3+l][(ks*8+nt)*32+lane]
__device__ float g_pre[MM * DD * 2];       // seg-0 totals per (m,d,e)

// ---------------- bf16 split helpers ----------------
__device__ __forceinline__ uint32_t pk(unsigned short a, unsigned short b) {
    return (uint32_t)a | ((uint32_t)b << 16);
}
__device__ __forceinline__ void split2(float fx, float fy, uint32_t& h, uint32_t& l) {
    __nv_bfloat16 h0 = __float2bfloat16(fx), h1 = __float2bfloat16(fy);
    h = pk(__bfloat16_as_ushort(h0), __bfloat16_as_ushort(h1));
    l = pk(__bfloat16_as_ushort(__float2bfloat16(fx - __bfloat162float(h0))),
           __bfloat16_as_ushort(__float2bfloat16(fy - __bfloat162float(h1))));
}
__device__ __forceinline__ void mma_bf16(float* d, uint32_t a0, uint32_t a1,
                                         uint32_t a2, uint32_t a3,
                                         uint32_t b0, uint32_t b1) {
    asm volatile(
        "mma.sync.aligned.m16n8k16.row.col.f32.bf16.bf16.f32 "
        "{%0,%1,%2,%3},{%4,%5,%6,%7},{%8,%9},{%0,%1,%2,%3};"
        : "+f"(d[0]), "+f"(d[1]), "+f"(d[2]), "+f"(d[3])
        : "r"(a0), "r"(a1), "r"(a2), "r"(a3), "r"(b0), "r"(b1));
}

#define MLP_SMEM (4608 * 4)   // output staging only (18.4KB)

// ---------------- Kernel 0: precompute W fragments + zero g_pre -----------
__global__ void __launch_bounds__(256) k_wprep(
    const float* __restrict__ wq_w, const float* __restrict__ wk_w)
{
    const int ul = blockIdx.x;          // 0..14
    const int u = ul / 3, l = ul % 3;
    const float* W = (u == 0) ? wq_w : wk_w + (size_t)(u - 1) * 3 * DD * DD;
    const float* Wlay = W + (size_t)l * DD * DD;

    const int tid = threadIdx.x;
    const int w = tid >> 5, lane = tid & 31;
    const int g = lane >> 2, q = lane & 3;
    const int n = w * 8 + g;

    if (ul == 0) {                      // zero the seg-0 totals each launch
        g_pre[tid] = 0.0f;
        g_pre[tid + 256] = 0.0f;
    }

    #pragma unroll
    for (int ks = 0; ks < 4; ks++) {
        const float* wp = Wlay + (ks * 16 + 2 * q) * 64 + n;
        float b00 = wp[0],      b01 = wp[64];
        float b10 = wp[8 * 64], b11 = wp[9 * 64];
        uint4 v;
        split2(b00, b01, v.x, v.z);
        split2(b10, b11, v.y, v.w);
        g_WF[ul * 1024 + (ks * 8 + w) * 32 + lane] = v;
    }
}

// ---------------- Kernel 1: 5 MLPs, 64-row tiles, register-resident A -----
// grid (T/64, 5), 128 threads (4 warps); warp w owns rows w*16 .. w*16+15.
__global__ void __launch_bounds__(128, 4) k_mlp(
    const float* __restrict__ X,
    const float* __restrict__ wq_b, const float* __restrict__ wk_b)
{
    extern __shared__ __align__(16) float St[];   // staging [4608]

    const int tid  = threadIdx.x;
    const int w    = tid >> 5;
    const int lane = tid & 31;
    const int g    = lane >> 2;   // 0..7
    const int q    = lane & 3;    // 0..3
    const int u    = blockIdx.y;
    const int base = blockIdx.x * 64;
    const int m_in = (u == 0) ? 0 : (u - 1);
    const float* B = (u == 0) ? wq_b : wk_b + (size_t)(u - 1) * 3 * DD;

    uint4 AH[4], AL[4];
    {
        const int r0 = base + w * 16 + g;
        const float* x0 = X + ((size_t)m_in * TT + r0) * DD;
        const float* x1 = x0 + 8 * DD;
        #pragma unroll
        for (int ks = 0; ks < 4; ks++) {
            float2 a0 = *(const float2*)(x0 + ks * 16 + 2 * q);
            float2 a2 = *(const float2*)(x0 + ks * 16 + 8 + 2 * q);
            float2 a1 = *(const float2*)(x1 + ks * 16 + 2 * q);
            float2 a3 = *(const float2*)(x1 + ks * 16 + 8 + 2 * q);
            if (u >= 1) {
                if (ks == 0 && q == 0) {
                    ((float2*)g_V2)[(size_t)m_in * TT + r0]     = a0;
                    ((float2*)g_V2)[(size_t)m_in * TT + r0 + 8] = a1;
                }
                if (ks == 3 && q == 3) {
                    g_T2[(size_t)m_in * TT + r0]     = a2.y;
                    g_T2[(size_t)m_in * TT + r0 + 8] = a3.y;
                }
            }
            split2(a0.x, a0.y, AH[ks].x, AL[ks].x);
            split2(a2.x, a2.y, AH[ks].y, AL[ks].y);
            split2(a1.x, a1.y, AH[ks].z, AL[ks].z);
            split2(a3.x, a3.y, AH[ks].w, AL[ks].w);
        }
    }

    #pragma unroll
    for (int l = 0; l < 3; l++) {
        const uint4* wf = g_WF + (u * 3 + l) * 1024;

        float d[8][4];
        #pragma unroll
        for (int nt = 0; nt < 8; nt++)
            #pragma unroll
            for (int j = 0; j < 4; j++) d[nt][j] = 0.0f;

        #pragma unroll
        for (int ks = 0; ks < 4; ks++) {
            #pragma unroll
            for (int nt = 0; nt < 8; nt++) {
                const uint4 b = __ldg(wf + (ks * 8 + nt) * 32 + lane);
                mma_bf16(d[nt], AH[ks].x, AH[ks].z, AH[ks].y, AH[ks].w, b.x, b.y);
                mma_bf16(d[nt], AH[ks].x, AH[ks].z, AH[ks].y, AH[ks].w, b.z, b.w);
                mma_bf16(d[nt], AL[ks].x, AL[ks].z, AL[ks].y, AL[ks].w, b.x, b.y);
            }
        }

        if (l < 2) {
            #pragma unroll
            for (int ksn = 0; ksn < 4; ksn++) {
                const int nt0 = 2 * ksn, nt1 = nt0 + 1;
                const int c0 = nt0 * 8 + 2 * q, c1 = nt1 * 8 + 2 * q;
                float2 b0 = __ldg((const float2*)(B + l * 64 + c0));
                float2 b1 = __ldg((const float2*)(B + l * 64 + c1));
                float f0x = fmaxf(d[nt0][0] + b0.x, 0.0f);
                float f0y = fmaxf(d[nt0][1] + b0.y, 0.0f);
                float f1x = fmaxf(d[nt1][0] + b1.x, 0.0f);
                float f1y = fmaxf(d[nt1][1] + b1.y, 0.0f);
                float f2x = fmaxf(d[nt0][2] + b0.x, 0.0f);
                float f2y = fmaxf(d[nt0][3] + b0.y, 0.0f);
                float f3x = fmaxf(d[nt1][2] + b1.x, 0.0f);
                float f3y = fmaxf(d[nt1][3] + b1.y, 0.0f);
                split2(f0x, f0y, AH[ksn].x, AL[ksn].x);
                split2(f1x, f1y, AH[ksn].y, AL[ksn].y);
                split2(f2x, f2y, AH[ksn].z, AL[ksn].z);
                split2(f3x, f3y, AH[ksn].w, AL[ksn].w);
            }
        } else {
            const int row0 = w * 16 + g;   // 0..63
            if (u == 0) {
                #pragma unroll
                for (int nt = 0; nt < 8; nt++) {
                    const int col = nt * 8 + 2 * q;
                    float2 bb = __ldg((const float2*)(B + 128 + col));
                    St[row0 * 72 + col]           = d[nt][0] + bb.x;
                    St[row0 * 72 + col + 1]       = d[nt][1] + bb.y;
                    St[(row0 + 8) * 72 + col]     = d[nt][2] + bb.x;
                    St[(row0 + 8) * 72 + col + 1] = d[nt][3] + bb.y;
                }
                __syncthreads();
                const int row = tid >> 1, c0 = (tid & 1) * 32;
                #pragma unroll
                for (int qq = 0; qq < 8; qq++) {
                    float4 v = *(float4*)&St[row * 72 + c0 + qq * 4];
                    *(float4*)&g_Q[(size_t)(base + row) * 64 + c0 + qq * 4] = v;
                }
            } else {
                #pragma unroll
                for (int nt = 0; nt < 8; nt++) {
                    const int col = nt * 8 + 2 * q;
                    float2 bb = __ldg((const float2*)(B + 128 + col));
                    St[col * 68 + row0]           = d[nt][0] + bb.x;
                    St[(col + 1) * 68 + row0]     = d[nt][1] + bb.y;
                    St[col * 68 + row0 + 8]       = d[nt][2] + bb.x;
                    St[(col + 1) * 68 + row0 + 8] = d[nt][3] + bb.y;
                }
                __syncthreads();
                const int col = tid >> 1, l2 = tid & 1;
                const size_t cb = (size_t)((u - 1) * 64 + col) * TT + base;
                #pragma unroll
                for (int qq = 0; qq < 8; qq++) {
                    const int row = l2 * 4 + qq * 8;
                    float4 v = *(float4*)&St[col * 68 + row];
                    *(float4*)&g_KT[cb + row] = v;
                }
                // seg-0 K.V partial sums -> g_pre (for scan's seg-1 base)
                if (blockIdx.x < 64) {
                    const float2* vv = (const float2*)g_V2
                        + (size_t)m_in * TT + base + l2 * 32;
                    float s0 = 0.0f, s1 = 0.0f;
                    #pragma unroll
                    for (int j = 0; j < 32; j++) {
                        float kv = St[col * 68 + l2 * 32 + j];
                        float2 v = __ldg(vv + j);
                        s0 += kv * v.x;
                        s1 += kv * v.y;
                    }
                    s0 += __shfl_xor_sync(0xffffffffu, s0, 1);
                    s1 += __shfl_xor_sync(0xffffffffu, s1, 1);
                    if (!l2) {
                        atomicAdd(&g_pre[((u - 1) * 64 + col) * 2 + 0], s0);
                        atomicAdd(&g_pre[((u - 1) * 64 + col) * 2 + 1], s1);
                    }
                }
            }
        }
    }
}

// ---------------- Kernel 2: fused scan (2 channels/block) + searchsorted --
// blocks 0..255: scan. blockIdx = m*64 + dpair*2 + seg; channels dpair, dpair+32.
// blocks 256..383: searchsorted + zero output.
__global__ void __launch_bounds__(256) k_scanIdx(float* __restrict__ out)
{
    const int tid = threadIdx.x;

    if (blockIdx.x >= 256) {
        const int gid = (blockIdx.x - 256) * 256 + tid;   // [0, MM*TT)
        if (gid < TT)
            ((float2*)out)[gid] = make_float2(0.0f, 0.0f);
        const int t = gid & (TT - 1);
        const int m = gid >> 13;
        const float key = g_T2[t];
        const float* arr = g_T2 + (size_t)m * TT;
        int lo = 0, hi = TT;
        while (lo < hi) {
            int mid = (lo + hi) >> 1;
            if (arr[mid] <= key) lo = mid + 1; else hi = mid;
        }
        g_idx[gid] = lo - 1;
        return;
    }

    const int m   = blockIdx.x >> 6;
    const int dp  = (blockIdx.x >> 1) & 31;
    const int seg = blockIdx.x & 1;
    const int lane = tid & 31, wid = tid >> 5;
    const int t0 = seg * SEG + tid * 16;

    const float4* vp = (const float4*)(g_V2 + (size_t)m * TT * 2);
    __shared__ float ws0[8], ws1[8];

    #pragma unroll
    for (int c = 0; c < 2; c++) {
        if (c) __syncthreads();          // protect ws reuse across passes
        const int ch = m * 64 + dp + 32 * c;
        const float4* kp = (const float4*)(g_KT + (size_t)ch * TT);

        float pre0 = 0.0f, pre1 = 0.0f;
        if (seg) {
            float2 p = __ldg((const float2*)g_pre + ch);
            pre0 = p.x; pre1 = p.y;
        }

        float kk[16];
        #pragma unroll
        for (int q = 0; q < 4; q++) {
            float4 k4 = kp[(t0 >> 2) + q];
            kk[q * 4 + 0] = k4.x; kk[q * 4 + 1] = k4.y;
            kk[q * 4 + 2] = k4.z; kk[q * 4 + 3] = k4.w;
        }
        float p0[16], p1[16];
        #pragma unroll
        for (int q = 0; q < 8; q++) {
            float4 v = vp[(t0 >> 1) + q];
            p0[q * 2]     = kk[q * 2]     * v.x;
            p1[q * 2]     = kk[q * 2]     * v.y;
            p0[q * 2 + 1] = kk[q * 2 + 1] * v.z;
            p1[q * 2 + 1] = kk[q * 2 + 1] * v.w;
        }
        #pragma unroll
        for (int e = 1; e < 16; e++) { p0[e] += p0[e - 1]; p1[e] += p1[e - 1]; }

        float s0 = p0[15], s1 = p1[15];
        const float t00 = s0, t11 = s1;
        #pragma unroll
        for (int off = 1; off < 32; off <<= 1) {
            float n0 = __shfl_up_sync(0xffffffffu, s0, off);
            float n1 = __shfl_up_sync(0xffffffffu, s1, off);
            if (lane >= off) { s0 += n0; s1 += n1; }
        }
        if (lane == 31) { ws0[wid] = s0; ws1[wid] = s1; }
        __syncthreads();
        float base0 = pre0, base1 = pre1;
        #pragma unroll
        for (int w = 0; w < 7; w++) {
            if (w < wid) { base0 += ws0[w]; base1 += ws1[w]; }
        }
        base0 += s0 - t00;
        base1 += s1 - t11;

        float4* sp = (float4*)(g_S + (size_t)ch * TT * 2);
        #pragma unroll
        for (int q = 0; q < 8; q++) {
            float4 o;
            o.x = base0 + p0[q * 2];     o.y = base1 + p1[q * 2];
            o.z = base0 + p0[q * 2 + 1]; o.w = base1 + p1[q * 2 + 1];
            sp[(t0 >> 1) + q] = o;
        }
    }
}

// ---------------- Kernel 3: gather + contract + atomic accumulate ---------
// grid (T/64, M*2): blockIdx.y = m*2 + dhalf.
__global__ void __launch_bounds__(256) k_gath(float* __restrict__ out)
{
    __shared__ float Qs[64 * 33];
    __shared__ float2 red[256];

    const int m   = blockIdx.y >> 1;
    const int dh  = blockIdx.y & 1;
    const int t0  = blockIdx.x * 64;
    const int tid = threadIdx.x;
    const int lt  = tid & 63;
    const int dq  = tid >> 6;

    {
        const int r = tid >> 2, c4 = tid & 3;
        const float* src = g_Q + (size_t)(t0 + r) * 64 + dh * 32 + c4 * 8;
        #pragma unroll
        for (int j = 0; j < 2; j++) {
            float4 v = ((const float4*)src)[j];
            const int c = c4 * 8 + j * 4;
            Qs[r * 33 + c + 0] = v.x;
            Qs[r * 33 + c + 1] = v.y;
            Qs[r * 33 + c + 2] = v.z;
            Qs[r * 33 + c + 3] = v.w;
        }
    }

    const int idx = g_idx[(size_t)m * TT + t0 + lt];
    __syncthreads();

    float a0 = 0.0f, a1 = 0.0f;
    if (idx >= 0) {
        const float2* sp = (const float2*)g_S
            + (size_t)(m * 64 + dh * 32 + dq * 8) * TT + idx;
        #pragma unroll
        for (int dd = 0; dd < 8; dd++) {
            float q  = Qs[lt * 33 + dq * 8 + dd];
            float2 s = sp[(size_t)dd * TT];
            a0 += q * s.x;
            a1 += q * s.y;
        }
    }
    red[tid] = make_float2(a0, a1);
    __syncthreads();

    if (dq == 0) {
        float ax = 0.0f, ay = 0.0f;
        #pragma unroll
        for (int q = 0; q < 4; q++) {
            float2 v = red[lt + 64 * q];
            ax += v.x; ay += v.y;
        }
        atomicAdd(out + (size_t)(t0 + lt) * 2 + 0, ax);
        atomicAdd(out + (size_t)(t0 + lt) * 2 + 1, ay);
    }
}

// ---------------- launch ----------------
extern "C" void kernel_launch(void* const* d_in, const int* in_sizes, int n_in,
                              void* d_out, int out_size)
{
    const float* X    = (const float*)d_in[0];
    const float* wq_w = (const float*)d_in[1];
    const float* wq_b = (const float*)d_in[2];
    const float* wk_w = (const float*)d_in[3];
    const float* wk_b = (const float*)d_in[4];
    float* out = (float*)d_out;

    k_wprep  <<<15, 256>>>(wq_w, wk_w);
    k_mlp    <<<dim3(TT / 64, 5), 128, MLP_SMEM>>>(X, wq_b, wk_b);
    k_scanIdx<<<256 + 128, 256>>>(out);
    k_gath   <<<dim3(TT / 64, MM * 2), 256>>>(out);
}